// round 9
// baseline (speedup 1.0000x reference)
#include <cuda_runtime.h>

// GridCellRouter: H=W=4096, N=16,777,216 cells, 16 iterations.
// Identity:  c_t = S*c_{t-1} + c_{t-2}  (scatter into the c_{t-2} buffer),
//            c_0 = runoff, c_{-1} = 0,  answer A_16 = c_16 + c_15.
//
// Round 9 fix: this iteration's src IS next iteration's atomic dst.
// Reading it with .cs demoted it out of L2 and forced ~240 MB/iter of
// dst-sector thrash (ncu: 369 MB DRAM vs 128 MB mandatory). So X/Y are
// read with DEFAULT policy (they together ~fill L2 at 128 MB); only idx
// (true one-shot stream) is evict-first.

#define N_CELLS (4096 * 4096)
#define ITERS 16

__device__ float g_x[N_CELLS];   // 64 MB ping
__device__ float g_y[N_CELLS];   // 64 MB pong

__device__ __forceinline__ int4 ldcs_i4(const int4* p) {
    int4 v;
    asm volatile("ld.global.cs.v4.b32 {%0,%1,%2,%3}, [%4];"
                 : "=r"(v.x), "=r"(v.y), "=r"(v.z), "=r"(v.w) : "l"(p));
    return v;
}

// X = runoff (= c_0), Y = 0 (= c_{-1})
__global__ void init_kernel(const float4* __restrict__ runoff,
                            float4* __restrict__ x,
                            float4* __restrict__ y, int n4) {
    int i = blockIdx.x * blockDim.x + threadIdx.x;
    if (i >= n4) return;
    x[i] = runoff[i];
    y[i] = make_float4(0.f, 0.f, 0.f, 0.f);
}

// dst += S * src.  8 elements per thread (2x float4/int4) for MLP.
// src read with DEFAULT policy (keeps it L2-resident for its next-iter
// role as dst); idx streamed evict-first.
__global__ void scatter_kernel(const float* __restrict__ src,
                               const int* __restrict__ idx,
                               float* __restrict__ dst, int n8) {
    int t = blockIdx.x * blockDim.x + threadIdx.x;
    if (t >= n8) return;
    const float4* s4 = reinterpret_cast<const float4*>(src) + 2 * t;
    const int4*   i4 = reinterpret_cast<const int4*>(idx) + 2 * t;
    float4 c0 = s4[0];
    float4 c1 = s4[1];
    int4 d0 = ldcs_i4(i4 + 0);
    int4 d1 = ldcs_i4(i4 + 1);
    atomicAdd(dst + d0.x, c0.x);   // result unused -> RED.E.ADD.F32
    atomicAdd(dst + d0.y, c0.y);
    atomicAdd(dst + d0.z, c0.z);
    atomicAdd(dst + d0.w, c0.w);
    atomicAdd(dst + d1.x, c1.x);
    atomicAdd(dst + d1.y, c1.y);
    atomicAdd(dst + d1.z, c1.z);
    atomicAdd(dst + d1.w, c1.w);
}

// out = c_16 + c_15
__global__ void final_kernel(const float4* __restrict__ x,
                             const float4* __restrict__ y,
                             float4* __restrict__ out, int n4) {
    int t = blockIdx.x * blockDim.x + threadIdx.x;
    if (t >= n4) return;
    float4 a = x[t];
    float4 b = y[t];
    float4 o;
    o.x = a.x + b.x; o.y = a.y + b.y; o.z = a.z + b.z; o.w = a.w + b.w;
    out[t] = o;
}

extern "C" void kernel_launch(void* const* d_in, const int* in_sizes, int n_in,
                              void* d_out, int out_size) {
    const float* runoff = (const float*)d_in[0];
    const int* flow_idx = (const int*)d_in[1];
    float* out = (float*)d_out;

    float* X = nullptr;
    float* Y = nullptr;
    cudaGetSymbolAddress((void**)&X, g_x);
    cudaGetSymbolAddress((void**)&Y, g_y);

    const int n4 = N_CELLS / 4;   // 4,194,304
    const int n8 = N_CELLS / 8;   // 2,097,152
    const int threads = 256;
    const int blocks4 = (n4 + threads - 1) / threads;
    const int blocks8 = (n8 + threads - 1) / threads;

    // X = c_0 = runoff, Y = c_{-1} = 0
    init_kernel<<<blocks4, threads>>>((const float4*)runoff, (float4*)X, (float4*)Y, n4);

    // c_t = S*c_{t-1} + c_{t-2}, scattering into the c_{t-2} buffer in place.
    for (int it = 0; it < ITERS; ++it) {
        if ((it & 1) == 0)
            scatter_kernel<<<blocks8, threads>>>(X, flow_idx, Y, n8);
        else
            scatter_kernel<<<blocks8, threads>>>(Y, flow_idx, X, n8);
    }
    // After 16 iters: X = c_16, Y = c_15.
    final_kernel<<<blocks4, threads>>>((const float4*)X, (const float4*)Y, (float4*)out, n4);
}

// round 10
// speedup vs baseline: 1.7733x; 1.7733x over previous
#include <cuda_runtime.h>

// GridCellRouter: H=W=4096, N=16,777,216 cells, 16 iterations.
//
// Let (S u)[j] = sum_{i: idx[i]=j} u[i].  Reference recurrence:
//   c_t = S c_{t-1} + c_{t-2},  c_0 = runoff, c_{-1} = 0,  answer A_16 = c_16 + c_15.
// Define b_t = c_t + c_{t-1}  (same recurrence, b_0 = r, b_1 = (S+I) r); answer = b_16.
// Even subsequence B_k = b_{2k} satisfies the DOUBLED recurrence
//   B_{k+1} = (S^2 + 2 I) B_k - B_{k-1},   B_0 = r,  B_1 = (S^2 + S + I) r,
// and S^2 is one scatter through the composed map idx2[i] = idx[idx[i]].
// => 16 scatter passes collapse to 1 compose + 9 scatters + 7 cheap seq passes.
// (Scatter passes are LSU-issue bound at ~114us and cache-policy invariant —
//  rounds 1-9 — so fewer passes is the only lever.)

#define N_CELLS (4096 * 4096)

__device__ float g_x[N_CELLS];     // 64 MB
__device__ float g_y[N_CELLS];     // 64 MB
__device__ int   g_idx2[N_CELLS];  // 64 MB composed map

__device__ __forceinline__ float4 ldcs_f4(const float4* p) {
    float4 v;
    asm volatile("ld.global.cs.v4.f32 {%0,%1,%2,%3}, [%4];"
                 : "=f"(v.x), "=f"(v.y), "=f"(v.z), "=f"(v.w) : "l"(p));
    return v;
}
__device__ __forceinline__ int4 ldcs_i4(const int4* p) {
    int4 v;
    asm volatile("ld.global.cs.v4.b32 {%0,%1,%2,%3}, [%4];"
                 : "=r"(v.x), "=r"(v.y), "=r"(v.z), "=r"(v.w) : "l"(p));
    return v;
}

// idx2[i] = idx[idx[i]]  (one-time composed map; random gather)
__global__ void compose_kernel(const int* __restrict__ idx,
                               int4* __restrict__ idx2, int n4) {
    int t = blockIdx.x * blockDim.x + threadIdx.x;
    if (t >= n4) return;
    int4 v = ldcs_i4(reinterpret_cast<const int4*>(idx) + t);
    int4 w;
    w.x = __ldg(idx + v.x);
    w.y = __ldg(idx + v.y);
    w.z = __ldg(idx + v.z);
    w.w = __ldg(idx + v.w);
    idx2[t] = w;
}

// X = r, Y = r   (X becomes B_1 after b1_kernel; Y = B_0)
__global__ void init_kernel(const float4* __restrict__ r,
                            float4* __restrict__ x,
                            float4* __restrict__ y, int n4) {
    int t = blockIdx.x * blockDim.x + threadIdx.x;
    if (t >= n4) return;
    float4 v = ldcs_f4(r + t);
    x[t] = v;
    y[t] = v;
}

// X += S r + S^2 r   (fused double scatter of runoff through idx and idx2)
__global__ void b1_kernel(const float* __restrict__ r,
                          const int* __restrict__ idx,
                          const int* __restrict__ idx2,
                          float* __restrict__ x, int n4) {
    int t = blockIdx.x * blockDim.x + threadIdx.x;
    if (t >= n4) return;
    float4 c = ldcs_f4(reinterpret_cast<const float4*>(r) + t);
    int4 a = ldcs_i4(reinterpret_cast<const int4*>(idx) + t);
    int4 b = ldcs_i4(reinterpret_cast<const int4*>(idx2) + t);
    atomicAdd(x + a.x, c.x);  atomicAdd(x + a.y, c.y);
    atomicAdd(x + a.z, c.z);  atomicAdd(x + a.w, c.w);
    atomicAdd(x + b.x, c.x);  atomicAdd(x + b.y, c.y);
    atomicAdd(x + b.z, c.z);  atomicAdd(x + b.w, c.w);
}

// dst = 2*cur - prev   (elementwise; dst may alias prev)
__global__ void fix_kernel(const float4* __restrict__ cur,
                           const float4* __restrict__ prev,
                           float4* __restrict__ dst, int n4) {
    int t = blockIdx.x * blockDim.x + threadIdx.x;
    if (t >= n4) return;
    float4 a = ldcs_f4(cur + t);
    float4 b = ldcs_f4(prev + t);
    float4 o;
    o.x = 2.f * a.x - b.x;  o.y = 2.f * a.y - b.y;
    o.z = 2.f * a.z - b.z;  o.w = 2.f * a.w - b.w;
    dst[t] = o;
}

// dst[idx2[i]] += src[i]   (the S^2 scatter)
__global__ void scatter_kernel(const float* __restrict__ src,
                               const int* __restrict__ idx2,
                               float* __restrict__ dst, int n4) {
    int t = blockIdx.x * blockDim.x + threadIdx.x;
    if (t >= n4) return;
    float4 c = ldcs_f4(reinterpret_cast<const float4*>(src) + t);
    int4 d = ldcs_i4(reinterpret_cast<const int4*>(idx2) + t);
    atomicAdd(dst + d.x, c.x);   // result unused -> RED.E.ADD.F32
    atomicAdd(dst + d.y, c.y);
    atomicAdd(dst + d.z, c.z);
    atomicAdd(dst + d.w, c.w);
}

extern "C" void kernel_launch(void* const* d_in, const int* in_sizes, int n_in,
                              void* d_out, int out_size) {
    const float* runoff = (const float*)d_in[0];
    const int* flow_idx = (const int*)d_in[1];
    float* out = (float*)d_out;

    float* X = nullptr;
    float* Y = nullptr;
    int* idx2 = nullptr;
    cudaGetSymbolAddress((void**)&X, g_x);
    cudaGetSymbolAddress((void**)&Y, g_y);
    cudaGetSymbolAddress((void**)&idx2, g_idx2);

    const int n4 = N_CELLS / 4;                       // 4,194,304
    const int threads = 256;
    const int blocks = (n4 + threads - 1) / threads;  // 16,384

    // Build composed map idx2 = idx o idx
    compose_kernel<<<blocks, threads>>>(flow_idx, (int4*)idx2, n4);

    // B_0 = r (in Y),  B_1 = (S^2 + S + I) r (in X)
    init_kernel<<<blocks, threads>>>((const float4*)runoff, (float4*)X, (float4*)Y, n4);
    b1_kernel<<<blocks, threads>>>(runoff, flow_idx, idx2, X, n4);

    // 7 doubling steps: B_{k+1} = (S^2 + 2I) B_k - B_{k-1}
    // Step: dst = 2*cur - prev; dst += S^2 cur. Last step writes d_out.
    float* cur = X;
    float* prev = Y;
    for (int k = 1; k <= 7; ++k) {
        float* dst = (k == 7) ? out : prev;
        fix_kernel<<<blocks, threads>>>((const float4*)cur, (const float4*)prev,
                                        (float4*)dst, n4);
        scatter_kernel<<<blocks, threads>>>(cur, idx2, dst, n4);
        prev = cur;
        cur = dst;
    }
    // cur == out holds B_8 = b_16 = c_16 + c_15 = A_16.
}